// round 12
// baseline (speedup 1.0000x reference)
#include <cuda_runtime.h>
#include <math.h>
#include <stdint.h>

#define B_ 8
#define N_ 16384
#define M_ 512
#define K_ 32
#define C_ 6
#define FPS_P 4096      // points per FPS CTA (4-CTA cluster)

// -------------------- scratch --------------------
__device__ int    g_center_idx[B_ * M_];
__device__ float  g_centers[B_ * M_ * 3];
__device__ int    g_gidx[B_ * M_ * K_];
__device__ float4 g_xyz[B_ * N_];
__device__ __align__(16) uint32_t g_wf1[2 * 4 * 128];
__device__ __align__(16) uint32_t g_wf2[8 * 8 * 128];
__device__ __align__(16) uint32_t g_wf3[16 * 16 * 128];
__device__ __align__(16) uint32_t g_wf4[32 * 24 * 128];
__device__ float g_ps[448], g_po[448];

// -------------------- helpers --------------------
__device__ __forceinline__ unsigned okey(float f) {
    unsigned u = __float_as_uint(f);
    unsigned mask = (u & 0x80000000u) ? 0xFFFFFFFFu : 0x80000000u;
    return u ^ mask;
}
__device__ __forceinline__ uint32_t f2tf32(float x) {
    uint32_t r;
    asm("cvt.rna.tf32.f32 %0, %1;" : "=r"(r) : "f"(x));
    return r;
}
__device__ __forceinline__ void mma_tf32(float* c, uint32_t a0, uint32_t a1,
                                         uint32_t a2, uint32_t a3,
                                         uint32_t b0, uint32_t b1) {
    asm volatile(
        "mma.sync.aligned.m16n8k8.row.col.f32.tf32.tf32.f32 "
        "{%0,%1,%2,%3}, {%4,%5,%6,%7}, {%8,%9}, {%0,%1,%2,%3};"
        : "+f"(c[0]), "+f"(c[1]), "+f"(c[2]), "+f"(c[3])
        : "r"(a0), "r"(a1), "r"(a2), "r"(a3), "r"(b0), "r"(b1));
}
__device__ __forceinline__ unsigned long long ffma2(
    unsigned long long a, unsigned long long b, unsigned long long c) {
    unsigned long long d;
    asm("fma.rn.f32x2 %0, %1, %2, %3;" : "=l"(d) : "l"(a), "l"(b), "l"(c));
    return d;
}
__device__ __forceinline__ unsigned long long addf2(
    unsigned long long a, unsigned long long b) {
    unsigned long long d;
    asm("add.rn.f32x2 %0, %1, %2;" : "=l"(d) : "l"(a), "l"(b));
    return d;
}
__device__ __forceinline__ unsigned long long mulf2(
    unsigned long long a, unsigned long long b) {
    unsigned long long d;
    asm("mul.rn.f32x2 %0, %1, %2;" : "=l"(d) : "l"(a), "l"(b));
    return d;
}
__device__ __forceinline__ unsigned long long dupf(float x) {
    unsigned long long d;
    asm("mov.b64 %0, {%1, %1};" : "=l"(d) : "f"(x));
    return d;
}
__device__ __forceinline__ float2 unpk(unsigned long long v) {
    float lo, hi;
    asm("mov.b64 {%0, %1}, %2;" : "=f"(lo), "=f"(hi) : "l"(v));
    return make_float2(lo, hi);
}
__device__ __forceinline__ uint32_t smem_u32(const void* p) {
    uint32_t a;
    asm("{ .reg .u64 t; cvta.to.shared.u64 t, %1; cvt.u32.u64 %0, t; }" : "=r"(a) : "l"(p));
    return a;
}
__device__ __forceinline__ uint32_t mapa_sh(uint32_t addr, uint32_t rank) {
    uint32_t r;
    asm("mapa.shared::cluster.u32 %0, %1, %2;" : "=r"(r) : "r"(addr), "r"(rank));
    return r;
}
__device__ __forceinline__ void stsc_f(uint32_t a, float v) {
    asm volatile("st.shared::cluster.f32 [%0], %1;" :: "r"(a), "f"(v) : "memory");
}
__device__ __forceinline__ void stsc_i(uint32_t a, int v) {
    asm volatile("st.shared::cluster.b32 [%0], %1;" :: "r"(a), "r"(v) : "memory");
}
__device__ __forceinline__ void stsc_rel(uint32_t a, int v) {
    asm volatile("st.release.cluster.shared::cluster.b32 [%0], %1;"
                 :: "r"(a), "r"(v) : "memory");
}
__device__ __forceinline__ int ld_acq(uint32_t a) {
    int v;
    asm volatile("ld.acquire.cluster.shared::cta.b32 %0, [%1];"
                 : "=r"(v) : "r"(a) : "memory");
    return v;
}
__device__ __forceinline__ void cluster_sync_() {
    asm volatile("barrier.cluster.arrive.aligned;" ::: "memory");
    asm volatile("barrier.cluster.wait.aligned;" ::: "memory");
}
__device__ __forceinline__ float dist2c(float cx, float cy, float cz, float cc2,
                                        float4 q) {
    float dot = __fmaf_rn(cx, q.x, __fmaf_rn(cy, q.y, __fmul_rn(cz, q.z)));
    return __fadd_rn(__fmaf_rn(-2.0f, dot, cc2), q.w);
}

// -------------------- merged weight-fragment prep --------------------
__device__ __forceinline__ void frag_one(const float* w, uint32_t* dst,
                                         int CIN, int DOUT, int idx) {
    int r = idx & 1, o = (idx >> 1) & 1, lane = (idx >> 2) & 31;
    int rest = idx >> 7;
    int np = DOUT / 16;
    int p = rest % np, kt = rest / np;
    int nt = 2 * p + o;
    int n = nt * 8 + (lane >> 2);
    int k = kt * 8 + (lane & 3) + 4 * r;
    float v = (k < CIN) ? w[(size_t)k * DOUT + n] : 0.0f;
    dst[idx] = f2tf32(v);
}
#define T1 (2 * 4 * 128)
#define T2 (8 * 8 * 128)
#define T3 (16 * 16 * 128)
#define T4 (32 * 24 * 128)
__global__ void prep_frag_all(const float* __restrict__ w1, const float* __restrict__ w2,
                              const float* __restrict__ w3, const float* __restrict__ w4) {
    int idx = blockIdx.x * blockDim.x + threadIdx.x;
    if (idx < T1) { frag_one(w1, g_wf1, 9, 64, idx); return; }
    idx -= T1;
    if (idx < T2) { frag_one(w2, g_wf2, 64, 128, idx); return; }
    idx -= T2;
    if (idx < T3) { frag_one(w3, g_wf3, 128, 256, idx); return; }
    idx -= T3;
    if (idx < T4) { frag_one(w4, g_wf4, 256, 384, idx); }
}

__global__ void prep_p_all(
    const float* __restrict__ b1, const float* __restrict__ g1,
    const float* __restrict__ be1, const float* __restrict__ m1, const float* __restrict__ v1,
    const float* __restrict__ b2, const float* __restrict__ g2,
    const float* __restrict__ be2, const float* __restrict__ m2, const float* __restrict__ v2,
    const float* __restrict__ b3, const float* __restrict__ g3,
    const float* __restrict__ be3, const float* __restrict__ m3, const float* __restrict__ v3)
{
    int i = blockIdx.x * blockDim.x + threadIdx.x;
    if (i >= 448) return;
    const float *b, *g, *be, *m, *v;
    int off;
    if (i < 64)       { b = b1; g = g1; be = be1; m = m1; v = v1; off = i; }
    else if (i < 192) { b = b2; g = g2; be = be2; m = m2; v = v2; off = i - 64; }
    else              { b = b3; g = g3; be = be3; m = m3; v = v3; off = i - 192; }
    float sc = g[off] * rsqrtf(v[off] + 1e-5f);
    g_ps[i] = sc;
    g_po[i] = (b[off] - m[off]) * sc + be[off];
}

// -------------------- pack xyz --------------------
__global__ void pack_kernel(const float* __restrict__ pts) {
    int i = blockIdx.x * blockDim.x + threadIdx.x;
    if (i < B_ * N_) {
        const float* p = pts + (size_t)i * C_;
        float x = p[0], y = p[1], z = p[2];
        g_xyz[i] = make_float4(x, y, z, x * x + y * y + z * z);
    }
}

// -------------------- FPS: 4-CTA cluster, seqnum DSMEM handshake ---------------
// smem floats: sx[4096] sy[4096] sz[4096] | rk[32] ri[32] @12288 |
//              mail 2x20 @12352 | seq 2x4 @12392
__global__ void __launch_bounds__(1024, 1) __cluster_dims__(4, 1, 1)
fps_kernel(float* centers_out) {
    extern __shared__ float fsm[];
    float* sx = fsm;
    float* sy = fsm + FPS_P;
    float* sz = fsm + 2 * FPS_P;
    unsigned* rk = (unsigned*)(fsm + 3 * FPS_P);   // 32
    unsigned* ri = rk + 32;                        // 32
    float* mail = fsm + 3 * FPS_P + 64;            // 2 x 20 floats
    int*   seq  = (int*)(mail + 40);               // 2 x 4

    const int b = blockIdx.x >> 2;
    const uint32_t rank = blockIdx.x & 3;
    const int tid = threadIdx.x;
    const int lane = tid & 31, wid = tid >> 5;
    const uint32_t mail_b = smem_u32(mail);
    const uint32_t seq_b  = smem_u32(seq);

    for (int n = tid; n < FPS_P; n += 1024) {
        float4 q = g_xyz[b * N_ + rank * FPS_P + n];
        sx[n] = q.x; sy[n] = q.y; sz[n] = q.z;
    }
    if (tid < 8) seq[tid] = 0;
    float dist[4];
#pragma unroll
    for (int j = 0; j < 4; j++) dist[j] = 1e10f;
    __syncthreads();

    // initial broadcast: point 0 coords (owner rank 0) -> all CTAs, buffer 1 slot 0
    if (rank == 0 && tid == 0) {
        float x = sx[0], y = sy[0], z = sz[0];
        for (uint32_t r = 0; r < 4; r++) {
            uint32_t a = mapa_sh(mail_b + 80, r);
            stsc_f(a + 32, x);
            stsc_f(a + 48, y);
            stsc_f(a + 64, z);
        }
    }
    cluster_sync_();    // seq init + initial broadcast visible cluster-wide
    int far = 0;
    float cx = mail[20 + 8], cy = mail[20 + 12], cz = mail[20 + 16];

    const unsigned long long* px = (const unsigned long long*)sx;
    const unsigned long long* py = (const unsigned long long*)sy;
    const unsigned long long* pz = (const unsigned long long*)sz;

    for (int it = 0; it < M_; ++it) {
        if (rank == 0 && tid == 0) {
            g_center_idx[b * M_ + it] = far;
            float* gc = g_centers + (size_t)(b * M_ + it) * 3;
            gc[0] = cx; gc[1] = cy; gc[2] = cz;
            if (centers_out) {
                float* oc = centers_out + (size_t)(b * M_ + it) * 3;
                oc[0] = cx; oc[1] = cy; oc[2] = cz;
            }
        }
        // packed scan: 2 pairs per thread (4 points)
        unsigned long long ncx = dupf(-cx), ncy = dupf(-cy), ncz = dupf(-cz);
        float bd = -1.0f; int bi = 0x7fffffff;
#pragma unroll
        for (int j = 0; j < 2; j++) {
            int pi = j * 1024 + tid;
            unsigned long long dxp = addf2(px[pi], ncx);
            unsigned long long dyp = addf2(py[pi], ncy);
            unsigned long long dzp = addf2(pz[pi], ncz);
            unsigned long long dp = ffma2(dyp, dyp, ffma2(dzp, dzp, mulf2(dxp, dxp)));
            float2 dv = unpk(dp);
            float nd0 = fminf(dist[2 * j],     dv.x);
            float nd1 = fminf(dist[2 * j + 1], dv.y);
            dist[2 * j] = nd0; dist[2 * j + 1] = nd1;
            if (nd0 > bd) { bd = nd0; bi = 2 * pi; }
            if (nd1 > bd) { bd = nd1; bi = 2 * pi + 1; }
        }
        unsigned key = okey(bd);
        unsigned kmax = __reduce_max_sync(0xffffffffu, key);
        unsigned cnd = (key == kmax) ? (unsigned)bi : 0xffffffffu;
        unsigned imin = __reduce_min_sync(0xffffffffu, cnd);
        if (lane == 0) { rk[wid] = kmax; ri[wid] = imin; }
        __syncthreads();
        const int p = it & 1;
        if (wid == 0) {
            unsigned k2 = rk[lane], i2 = ri[lane];
            unsigned kmax2 = __reduce_max_sync(0xffffffffu, k2);
            unsigned cnd2 = (k2 == kmax2) ? i2 : 0xffffffffu;
            unsigned imin2 = __reduce_min_sync(0xffffffffu, cnd2);
            if (lane == 0) {
                int li = (int)imin2;
                int gi = (int)rank * FPS_P + li;
                float x = sx[li], y = sy[li], z = sz[li];
                for (uint32_t r = 0; r < 4; r++) {
                    uint32_t a = mapa_sh(mail_b + p * 80 + rank * 4, r);
                    stsc_i(a, (int)kmax2);
                    stsc_i(a + 16, gi);
                    stsc_f(a + 32, x);
                    stsc_f(a + 48, y);
                    stsc_f(a + 64, z);
                    // release: payload above ordered before this seq store
                    stsc_rel(mapa_sh(seq_b + p * 16 + rank * 4, r), it + 1);
                }
            }
        }
        // wait for all 4 slots of buffer p to reach it+1
        if (tid < 4) {
            uint32_t sa = seq_b + p * 16 + tid * 4;
            while (ld_acq(sa) != it + 1) { }
        }
        __syncthreads();
        const unsigned* mk = (const unsigned*)(mail + p * 20);
        const int*      mi = (const int*)(mk + 4);
        const float*    md = (const float*)(mk + 8);
        unsigned wkey = mk[0]; int wi = mi[0]; int ws = 0;
#pragma unroll
        for (int s = 1; s < 4; s++) {
            unsigned k = mk[s]; int i = mi[s];
            if (k > wkey || (k == wkey && i < wi)) { wkey = k; wi = i; ws = s; }
        }
        far = wi;
        cx = md[ws]; cy = md[4 + ws]; cz = md[8 + ws];
    }
}

// -------------------- kNN: 4 centers/CTA, recompute-d2 --------------------
#define KNN_C 4
__global__ void __launch_bounds__(256) knn_kernel() {
    __shared__ int hist[KNN_C * 2048];
    __shared__ int scansm[256];
    __shared__ int selbin[KNN_C], lessc[KNN_C], candc[KNN_C];

    const int bid = blockIdx.x;
    const int gid0 = bid * KNN_C;
    const int b = gid0 >> 9;
    const int tid = threadIdx.x;

    float cx[KNN_C], cy[KNN_C], cz[KNN_C], cc2[KNN_C];
#pragma unroll
    for (int c = 0; c < KNN_C; c++) {
        cx[c] = g_centers[(gid0 + c) * 3 + 0];
        cy[c] = g_centers[(gid0 + c) * 3 + 1];
        cz[c] = g_centers[(gid0 + c) * 3 + 2];
        cc2[c] = __fmaf_rn(cx[c], cx[c], __fmaf_rn(cy[c], cy[c], __fmul_rn(cz[c], cz[c])));
    }
    for (int i = tid; i < KNN_C * 2048; i += 256) hist[i] = 0;
    __syncthreads();

    for (int n = tid; n < N_; n += 256) {
        float4 q = g_xyz[b * N_ + n];
#pragma unroll
        for (int c = 0; c < KNN_C; c++) {
            float d2 = dist2c(cx[c], cy[c], cz[c], cc2[c], q);
            atomicAdd(&hist[c * 2048 + (okey(d2) >> 21)], 1);
        }
    }
    __syncthreads();

    for (int c = 0; c < KNN_C; c++) {
        int* hc = hist + c * 2048;
        int s = 0;
#pragma unroll
        for (int t = 0; t < 8; ++t) s += hc[tid * 8 + t];
        scansm[tid] = s;
        __syncthreads();
        for (int off = 1; off < 256; off <<= 1) {
            int v = (tid >= off) ? scansm[tid - off] : 0;
            __syncthreads();
            scansm[tid] += v;
            __syncthreads();
        }
        int excl = scansm[tid] - s;
        if (excl < K_ && excl + s >= K_) {
            int cum = excl;
#pragma unroll
            for (int t = 0; t < 8; ++t) {
                int cc = hc[tid * 8 + t];
                if (cum + cc >= K_) { selbin[c] = tid * 8 + t; break; }
                cum += cc;
            }
        }
        __syncthreads();
    }
    if (tid < KNN_C) { lessc[tid] = 0; candc[tid] = 0; }
    __syncthreads();

    for (int n = tid; n < N_; n += 256) {
        float4 q = g_xyz[b * N_ + n];
#pragma unroll
        for (int c = 0; c < KNN_C; c++) {
            float d2 = dist2c(cx[c], cy[c], cz[c], cc2[c], q);
            unsigned u = okey(d2);
            int bin = (int)(u >> 21);
            if (bin < selbin[c]) {
                int p = atomicAdd(&lessc[c], 1);
                g_gidx[(size_t)(gid0 + c) * K_ + p] = n;
            } else if (bin == selbin[c]) {
                int e = atomicAdd(&candc[c], 1);
                if (e < 1024) {
                    hist[c * 2048 + e] = n;
                    hist[c * 2048 + 1024 + e] = (int)u;
                }
            }
        }
    }
    __syncthreads();

    for (int c = 0; c < KNN_C; c++) {
        int less = lessc[c];
        int cnt = candc[c];
        int need = K_ - less;
        int* gout = g_gidx + (size_t)(gid0 + c) * K_;
        if (cnt <= 1024) {
            int* cl = hist + c * 2048;
            for (int i = tid; i < cnt; i += 256) {
                int ni = cl[i];
                unsigned ui = (unsigned)cl[1024 + i];
                int rnk = 0;
                for (int j = 0; j < cnt; ++j) {
                    unsigned uj = (unsigned)cl[1024 + j];
                    int nj = cl[j];
                    rnk += (uj < ui || (uj == ui && nj < ni)) ? 1 : 0;
                }
                if (rnk < need) gout[less + rnk] = ni;
            }
        } else if (tid == 0) {
            int cc = 0;
            for (int n = 0; n < N_ && cc < need; ++n) {
                float4 q = g_xyz[b * N_ + n];
                float d2 = dist2c(cx[c], cy[c], cz[c], cc2[c], q);
                if ((int)(okey(d2) >> 21) == selbin[c]) { gout[less + cc] = n; ++cc; }
            }
        }
    }
}

// -------------------- mma.sync tf32 encoder (R8 version) --------------------
template<int KT, int NPH, int NPT, int SIN, int SOUT>
__device__ __forceinline__ void mma_layer_bn(
    const uint32_t* __restrict__ As, uint32_t* __restrict__ Ds,
    const uint32_t* __restrict__ wf, int p0,
    const float* __restrict__ ps, const float* __restrict__ po,
    int warp, int lane)
{
    float acc[2 * NPH][4];
#pragma unroll
    for (int t = 0; t < 2 * NPH; t++)
#pragma unroll
        for (int q = 0; q < 4; q++) acc[t][q] = 0.0f;
    const int g = lane >> 2, tig = lane & 3;
    const int row = warp * 16 + g;
#pragma unroll 2
    for (int kt = 0; kt < KT; kt++) {
        const uint32_t* ap = As + row * SIN + kt * 8 + tig;
        uint32_t a0 = ap[0], a2 = ap[4];
        uint32_t a1 = ap[8 * SIN], a3 = ap[8 * SIN + 4];
        const uint4* wp = (const uint4*)wf + ((size_t)(kt * NPT + p0)) * 32 + lane;
#pragma unroll
        for (int pp = 0; pp < NPH; pp++) {
            uint4 W = __ldg(wp + pp * 32);
            mma_tf32(acc[2 * pp],     a0, a1, a2, a3, W.x, W.y);
            mma_tf32(acc[2 * pp + 1], a0, a1, a2, a3, W.z, W.w);
        }
    }
#pragma unroll
    for (int t = 0; t < 2 * NPH; t++) {
        int j0 = (p0 * 2 + t) * 8 + 2 * tig;
        float s0 = __ldg(ps + j0), s1 = __ldg(ps + j0 + 1);
        float q0 = __ldg(po + j0), q1 = __ldg(po + j0 + 1);
        uint32_t* d0 = Ds + row * SOUT + j0;
        uint32_t* d1 = Ds + (row + 8) * SOUT + j0;
        d0[0] = f2tf32(fmaxf(fmaf(acc[t][0], s0, q0), 0.0f));
        d0[1] = f2tf32(fmaxf(fmaf(acc[t][1], s1, q1), 0.0f));
        d1[0] = f2tf32(fmaxf(fmaf(acc[t][2], s0, q0), 0.0f));
        d1[1] = f2tf32(fmaxf(fmaf(acc[t][3], s1, q1), 0.0f));
    }
}

template<int KT, int NPH, int NPT, int SIN>
__device__ __forceinline__ void mma_layer_max(
    const uint32_t* __restrict__ As, const uint32_t* __restrict__ wf, int p0,
    float* __restrict__ maxw, int warp, int lane)
{
    float acc[2 * NPH][4];
#pragma unroll
    for (int t = 0; t < 2 * NPH; t++)
#pragma unroll
        for (int q = 0; q < 4; q++) acc[t][q] = 0.0f;
    const int g = lane >> 2, tig = lane & 3;
    const int row = warp * 16 + g;
#pragma unroll 2
    for (int kt = 0; kt < KT; kt++) {
        const uint32_t* ap = As + row * SIN + kt * 8 + tig;
        uint32_t a0 = ap[0], a2 = ap[4];
        uint32_t a1 = ap[8 * SIN], a3 = ap[8 * SIN + 4];
        const uint4* wp = (const uint4*)wf + ((size_t)(kt * NPT + p0)) * 32 + lane;
#pragma unroll
        for (int pp = 0; pp < NPH; pp++) {
            uint4 W = __ldg(wp + pp * 32);
            mma_tf32(acc[2 * pp],     a0, a1, a2, a3, W.x, W.y);
            mma_tf32(acc[2 * pp + 1], a0, a1, a2, a3, W.z, W.w);
        }
    }
#pragma unroll
    for (int t = 0; t < 2 * NPH; t++) {
        int j0 = (p0 * 2 + t) * 8 + 2 * tig;
        float m0 = fmaxf(acc[t][0], acc[t][2]);
        float m1 = fmaxf(acc[t][1], acc[t][3]);
#pragma unroll
        for (int o = 4; o < 32; o <<= 1) {
            m0 = fmaxf(m0, __shfl_xor_sync(0xffffffffu, m0, o));
            m1 = fmaxf(m1, __shfl_xor_sync(0xffffffffu, m1, o));
        }
        if (g == 0) {
            maxw[warp * 392 + j0] = m0;
            maxw[warp * 392 + j0 + 1] = m1;
        }
    }
}

__global__ void __launch_bounds__(128, 2) encoder_kernel(
    const float* __restrict__ pts, const float* __restrict__ b4,
    float* __restrict__ tokens)
{
    extern __shared__ uint32_t esm[];
    uint32_t* X = esm;
    uint32_t* Y = esm + 16640;
    float* maxw = (float*)Y;

    const int tid = threadIdx.x;
    const int warp = tid >> 5, lane = tid & 31;

    if (tid < 64) {
        int gid2 = blockIdx.x * 2 + (tid >> 5);
        int b = gid2 >> 9;
        int n = g_gidx[(size_t)gid2 * K_ + (tid & 31)];
        const float* p = pts + (size_t)(b * N_ + n) * C_;
        float cx = g_centers[gid2 * 3 + 0];
        float cy = g_centers[gid2 * 3 + 1];
        float cz = g_centers[gid2 * 3 + 2];
        float x = p[0], y = p[1], z = p[2];
        uint32_t* r = Y + tid * 36;
        r[0] = f2tf32(x - cx); r[1] = f2tf32(y - cy); r[2] = f2tf32(z - cz);
        r[3] = f2tf32(x); r[4] = f2tf32(y); r[5] = f2tf32(z);
        r[6] = f2tf32(p[3]); r[7] = f2tf32(p[4]); r[8] = f2tf32(p[5]);
#pragma unroll
        for (int c = 9; c < 16; c++) r[c] = 0u;
    }
    __syncthreads();

    mma_layer_bn<2, 4, 4, 36, 68>(Y, X, g_wf1, 0, g_ps, g_po, warp, lane);
    __syncwarp();
    mma_layer_bn<8, 8, 8, 68, 132>(X, Y, g_wf2, 0, g_ps + 64, g_po + 64, warp, lane);
    __syncwarp();
    mma_layer_bn<16, 8, 16, 132, 260>(Y, X, g_wf3, 0, g_ps + 192, g_po + 192, warp, lane);
    mma_layer_bn<16, 8, 16, 132, 260>(Y, X, g_wf3, 8, g_ps + 192, g_po + 192, warp, lane);
    __syncwarp();
    __syncthreads();
    mma_layer_max<32, 12, 24, 260>(X, g_wf4, 0,  maxw, warp, lane);
    mma_layer_max<32, 12, 24, 260>(X, g_wf4, 12, maxw, warp, lane);
    __syncthreads();

    for (int i = tid; i < 768; i += 128) {
        int g = i / 384, col = i - g * 384;
        float mx = fmaxf(maxw[(2 * g) * 392 + col], maxw[(2 * g + 1) * 392 + col]);
        tokens[(size_t)(blockIdx.x * 2 + g) * 384 + col] = mx + __ldg(b4 + col);
    }
}

// -------------------- positional MLP: 8 centers/CTA --------------------
__global__ void __launch_bounds__(384) pos_kernel(
    const float* __restrict__ pw1, const float* __restrict__ pb1,
    const float* __restrict__ pw2, const float* __restrict__ pb2,
    float* __restrict__ tokens)
{
    __shared__ float h[8 * 128];
    const int gid0 = blockIdx.x * 8;
    const int tid = threadIdx.x;

    for (int idx = tid; idx < 8 * 128; idx += 384) {
        int c = idx >> 7, col = idx & 127;
        float cx = g_centers[(gid0 + c) * 3 + 0];
        float cy = g_centers[(gid0 + c) * 3 + 1];
        float cz = g_centers[(gid0 + c) * 3 + 2];
        float t = cx * __ldg(pw1 + col) + cy * __ldg(pw1 + 128 + col)
                + cz * __ldg(pw1 + 256 + col) + __ldg(pb1 + col);
        h[idx] = 0.5f * t * (1.0f + erff(t * 0.70710678118654752f));
    }
    __syncthreads();

    const int col = tid;
    float acc[8];
    float bj = __ldg(pb2 + col);
#pragma unroll
    for (int c = 0; c < 8; c++) acc[c] = bj;
#pragma unroll 2
    for (int k = 0; k < 128; ++k) {
        float w = __ldg(pw2 + (size_t)k * 384 + col);
#pragma unroll
        for (int c = 0; c < 8; c++)
            acc[c] = fmaf(h[c * 128 + k], w, acc[c]);
    }
#pragma unroll
    for (int c = 0; c < 8; c++)
        tokens[(size_t)(gid0 + c) * 384 + col] += acc[c];
}

// -------------------- launch --------------------
extern "C" void kernel_launch(void* const* d_in, const int* in_sizes, int n_in,
                              void* d_out, int out_size)
{
    const float* pts = (const float*)d_in[0];
    const float* w1 = (const float*)d_in[1],  *b1 = (const float*)d_in[2];
    const float* g1 = (const float*)d_in[3],  *be1 = (const float*)d_in[4];
    const float* m1 = (const float*)d_in[5],  *v1 = (const float*)d_in[6];
    const float* w2 = (const float*)d_in[7],  *b2 = (const float*)d_in[8];
    const float* g2 = (const float*)d_in[9],  *be2 = (const float*)d_in[10];
    const float* m2 = (const float*)d_in[11], *v2 = (const float*)d_in[12];
    const float* w3 = (const float*)d_in[13], *b3 = (const float*)d_in[14];
    const float* g3 = (const float*)d_in[15], *be3 = (const float*)d_in[16];
    const float* m3 = (const float*)d_in[17], *v3 = (const float*)d_in[18];
    const float* w4 = (const float*)d_in[19], *b4 = (const float*)d_in[20];
    const float* pw1 = (const float*)d_in[21], *pb1 = (const float*)d_in[22];
    const float* pw2 = (const float*)d_in[23], *pb2 = (const float*)d_in[24];

    float* out = (float*)d_out;
    float* tokens = out;
    float* centers_out =
        (out_size >= B_ * M_ * 384 + B_ * M_ * 3) ? (out + (size_t)B_ * M_ * 384)
                                                  : nullptr;

    const int FPS_SMEM = (3 * FPS_P + 64 + 40 + 8) * 4;   // 49,584 B
    const int ENC_SMEM = (16640 + 8448) * 4;              // 100,352 B

    cudaFuncSetAttribute(fps_kernel, cudaFuncAttributeMaxDynamicSharedMemorySize, FPS_SMEM);
    cudaFuncSetAttribute(encoder_kernel, cudaFuncAttributeMaxDynamicSharedMemorySize, ENC_SMEM);

    const int TOT = T1 + T2 + T3 + T4;
    prep_frag_all<<<(TOT + 255) / 256, 256>>>(w1, w2, w3, w4);
    prep_p_all<<<2, 256>>>(b1, g1, be1, m1, v1, b2, g2, be2, m2, v2, b3, g3, be3, m3, v3);
    pack_kernel<<<(B_ * N_ + 255) / 256, 256>>>(pts);
    fps_kernel<<<B_ * 4, 1024, FPS_SMEM>>>(centers_out);
    knn_kernel<<<B_ * M_ / KNN_C, 256>>>();
    encoder_kernel<<<B_ * M_ / 2, 128, ENC_SMEM>>>(pts, b4, tokens);
    pos_kernel<<<B_ * M_ / 8, 384>>>(pw1, pb1, pw2, pb2, tokens);
}

// round 13
// speedup vs baseline: 1.3483x; 1.3483x over previous
#include <cuda_runtime.h>
#include <math.h>
#include <stdint.h>

#define B_ 8
#define N_ 16384
#define M_ 512
#define K_ 32
#define C_ 6
#define FPS_P 4096      // points per FPS CTA (4-CTA cluster)

// -------------------- scratch --------------------
__device__ int    g_center_idx[B_ * M_];
__device__ float  g_centers[B_ * M_ * 3];
__device__ int    g_gidx[B_ * M_ * K_];
__device__ float4 g_xyz[B_ * N_];
__device__ __align__(16) uint32_t g_wf1[2 * 4 * 128];
__device__ __align__(16) uint32_t g_wf2[8 * 8 * 128];
__device__ __align__(16) uint32_t g_wf3[16 * 16 * 128];
__device__ __align__(16) uint32_t g_wf4[32 * 24 * 128];
__device__ float g_ps[448], g_po[448];

// -------------------- helpers --------------------
__device__ __forceinline__ unsigned okey(float f) {
    unsigned u = __float_as_uint(f);
    unsigned mask = (u & 0x80000000u) ? 0xFFFFFFFFu : 0x80000000u;
    return u ^ mask;
}
__device__ __forceinline__ uint32_t f2tf32(float x) {
    uint32_t r;
    asm("cvt.rna.tf32.f32 %0, %1;" : "=r"(r) : "f"(x));
    return r;
}
__device__ __forceinline__ void mma_tf32(float* c, uint32_t a0, uint32_t a1,
                                         uint32_t a2, uint32_t a3,
                                         uint32_t b0, uint32_t b1) {
    asm volatile(
        "mma.sync.aligned.m16n8k8.row.col.f32.tf32.tf32.f32 "
        "{%0,%1,%2,%3}, {%4,%5,%6,%7}, {%8,%9}, {%0,%1,%2,%3};"
        : "+f"(c[0]), "+f"(c[1]), "+f"(c[2]), "+f"(c[3])
        : "r"(a0), "r"(a1), "r"(a2), "r"(a3), "r"(b0), "r"(b1));
}
__device__ __forceinline__ uint32_t smem_u32(const void* p) {
    uint32_t a;
    asm("{ .reg .u64 t; cvta.to.shared.u64 t, %1; cvt.u32.u64 %0, t; }" : "=r"(a) : "l"(p));
    return a;
}
__device__ __forceinline__ uint32_t mapa_sh(uint32_t addr, uint32_t rank) {
    uint32_t r;
    asm("mapa.shared::cluster.u32 %0, %1, %2;" : "=r"(r) : "r"(addr), "r"(rank));
    return r;
}
__device__ __forceinline__ void stsc_f(uint32_t a, float v) {
    asm volatile("st.shared::cluster.f32 [%0], %1;" :: "r"(a), "f"(v) : "memory");
}
__device__ __forceinline__ void stsc_u64(uint32_t a, unsigned long long v) {
    asm volatile("st.shared::cluster.b64 [%0], %1;" :: "r"(a), "l"(v) : "memory");
}
__device__ __forceinline__ void stsc_u32(uint32_t a, unsigned v) {
    asm volatile("st.shared::cluster.b32 [%0], %1;" :: "r"(a), "r"(v) : "memory");
}
__device__ __forceinline__ void cluster_sync_() {
    asm volatile("barrier.cluster.arrive.aligned;" ::: "memory");
    asm volatile("barrier.cluster.wait.aligned;" ::: "memory");
}
__device__ __forceinline__ unsigned long long packu64(unsigned lo, unsigned hi) {
    unsigned long long d;
    asm("mov.b64 %0, {%1, %2};" : "=l"(d) : "r"(lo), "r"(hi));
    return d;
}
__device__ __forceinline__ float dist2c(float cx, float cy, float cz, float cc2,
                                        float4 q) {
    float dot = __fmaf_rn(cx, q.x, __fmaf_rn(cy, q.y, __fmul_rn(cz, q.z)));
    return __fadd_rn(__fmaf_rn(-2.0f, dot, cc2), q.w);
}

// -------------------- merged weight-fragment prep --------------------
__device__ __forceinline__ void frag_one(const float* w, uint32_t* dst,
                                         int CIN, int DOUT, int idx) {
    int r = idx & 1, o = (idx >> 1) & 1, lane = (idx >> 2) & 31;
    int rest = idx >> 7;
    int np = DOUT / 16;
    int p = rest % np, kt = rest / np;
    int nt = 2 * p + o;
    int n = nt * 8 + (lane >> 2);
    int k = kt * 8 + (lane & 3) + 4 * r;
    float v = (k < CIN) ? w[(size_t)k * DOUT + n] : 0.0f;
    dst[idx] = f2tf32(v);
}
#define T1 (2 * 4 * 128)
#define T2 (8 * 8 * 128)
#define T3 (16 * 16 * 128)
#define T4 (32 * 24 * 128)
__global__ void prep_frag_all(const float* __restrict__ w1, const float* __restrict__ w2,
                              const float* __restrict__ w3, const float* __restrict__ w4) {
    int idx = blockIdx.x * blockDim.x + threadIdx.x;
    if (idx < T1) { frag_one(w1, g_wf1, 9, 64, idx); return; }
    idx -= T1;
    if (idx < T2) { frag_one(w2, g_wf2, 64, 128, idx); return; }
    idx -= T2;
    if (idx < T3) { frag_one(w3, g_wf3, 128, 256, idx); return; }
    idx -= T3;
    if (idx < T4) { frag_one(w4, g_wf4, 256, 384, idx); }
}

__global__ void prep_p_all(
    const float* __restrict__ b1, const float* __restrict__ g1,
    const float* __restrict__ be1, const float* __restrict__ m1, const float* __restrict__ v1,
    const float* __restrict__ b2, const float* __restrict__ g2,
    const float* __restrict__ be2, const float* __restrict__ m2, const float* __restrict__ v2,
    const float* __restrict__ b3, const float* __restrict__ g3,
    const float* __restrict__ be3, const float* __restrict__ m3, const float* __restrict__ v3)
{
    int i = blockIdx.x * blockDim.x + threadIdx.x;
    if (i >= 448) return;
    const float *b, *g, *be, *m, *v;
    int off;
    if (i < 64)       { b = b1; g = g1; be = be1; m = m1; v = v1; off = i; }
    else if (i < 192) { b = b2; g = g2; be = be2; m = m2; v = v2; off = i - 64; }
    else              { b = b3; g = g3; be = be3; m = m3; v = v3; off = i - 192; }
    float sc = g[off] * rsqrtf(v[off] + 1e-5f);
    g_ps[i] = sc;
    g_po[i] = (b[off] - m[off]) * sc + be[off];
}

// -------------------- pack xyz --------------------
__global__ void pack_kernel(const float* __restrict__ pts) {
    int i = blockIdx.x * blockDim.x + threadIdx.x;
    if (i < B_ * N_) {
        const float* p = pts + (size_t)i * C_;
        float x = p[0], y = p[1], z = p[2];
        g_xyz[i] = make_float4(x, y, z, x * x + y * y + z * z);
    }
}

// -------------------- FPS: 4-CTA cluster (R9 skeleton, parallel wide stores) ----
// smem: sq float4[4096] | rk[32] ri[32] @16384 floats | mail u32[2][4][6] @16448
__global__ void __launch_bounds__(1024, 1) __cluster_dims__(4, 1, 1)
fps_kernel(float* centers_out) {
    extern __shared__ float fsm[];
    float4*   sq = (float4*)fsm;
    unsigned* rk = (unsigned*)(fsm + 16384);
    unsigned* ri = rk + 32;
    unsigned* mail = (unsigned*)(fsm + 16448);   // 2 buffers x 4 records x 6 u32
    const float* mailf = (const float*)mail;

    const int b = blockIdx.x >> 2;
    const uint32_t rank = blockIdx.x & 3;
    const int tid = threadIdx.x;
    const int lane = tid & 31, wid = tid >> 5;
    const uint32_t mail_b = smem_u32(mail);

    for (int n = tid; n < FPS_P; n += 1024)
        sq[n] = g_xyz[b * N_ + rank * FPS_P + n];
    float dist[4];
#pragma unroll
    for (int j = 0; j < 4; j++) dist[j] = 1e10f;
    __syncthreads();

    // initial broadcast: point 0 coords (owner rank 0) -> buffer 1 record 0
    if (rank == 0 && tid == 0) {
        float4 q = sq[0];
        for (uint32_t r = 0; r < 4; r++) {
            uint32_t a = mapa_sh(mail_b + 96, r);   // buffer 1, record 0
            stsc_u64(a + 8, packu64(__float_as_uint(q.x), __float_as_uint(q.y)));
            stsc_u32(a + 16, __float_as_uint(q.z));
        }
    }
    cluster_sync_();
    int far = 0;
    float cx = mailf[24 + 2], cy = mailf[24 + 3], cz = mailf[24 + 4];

    for (int it = 0; it < M_; ++it) {
        if (rank == 0 && tid == 0) {
            g_center_idx[b * M_ + it] = far;
            float* gc = g_centers + (size_t)(b * M_ + it) * 3;
            gc[0] = cx; gc[1] = cy; gc[2] = cz;
            if (centers_out) {
                float* oc = centers_out + (size_t)(b * M_ + it) * 3;
                oc[0] = cx; oc[1] = cy; oc[2] = cz;
            }
        }
        float bd = -1.0f; int bi = 0x7fffffff;
#pragma unroll
        for (int j = 0; j < 4; j++) {
            int n = j * 1024 + tid;
            float4 q = sq[n];
            float dx = q.x - cx, dy = q.y - cy, dz = q.z - cz;
            float d = dx * dx + dy * dy + dz * dz;
            float nd = fminf(dist[j], d);
            dist[j] = nd;
            if (nd > bd) { bd = nd; bi = n; }
        }
        unsigned key = okey(bd);
        unsigned kmax = __reduce_max_sync(0xffffffffu, key);
        unsigned cnd = (key == kmax) ? (unsigned)bi : 0xffffffffu;
        unsigned imin = __reduce_min_sync(0xffffffffu, cnd);
        if (lane == 0) { rk[wid] = kmax; ri[wid] = imin; }
        __syncthreads();
        const int p = it & 1;
        if (wid == 0) {
            unsigned k2 = rk[lane], i2 = ri[lane];
            unsigned kmax2 = __reduce_max_sync(0xffffffffu, k2);
            unsigned cnd2 = (k2 == kmax2) ? i2 : 0xffffffffu;
            unsigned imin2 = __reduce_min_sync(0xffffffffu, cnd2);
            // redux broadcasts: lanes 0..3 each ship the record to rank = lane
            if (lane < 4) {
                int li = (int)imin2;
                unsigned gi = rank * FPS_P + (unsigned)li;
                float4 q = sq[li];
                uint32_t a = mapa_sh(mail_b + p * 96 + rank * 24, (uint32_t)lane);
                stsc_u64(a, packu64(kmax2, gi));
                stsc_u64(a + 8, packu64(__float_as_uint(q.x), __float_as_uint(q.y)));
                stsc_u32(a + 16, __float_as_uint(q.z));
            }
        }
        cluster_sync_();   // orders remote stores; cluster-wide barrier
        const unsigned* mb = mail + p * 24;
        unsigned wkey = mb[0]; unsigned wi = mb[1]; int ws = 0;
#pragma unroll
        for (int s = 1; s < 4; s++) {
            unsigned k = mb[s * 6]; unsigned i = mb[s * 6 + 1];
            if (k > wkey || (k == wkey && i < wi)) { wkey = k; wi = i; ws = s; }
        }
        far = (int)(wi & (FPS_P - 1));
        // far is local only if winner rank == this rank; but coords come from mail:
        cx = __uint_as_float(mb[ws * 6 + 2]);
        cy = __uint_as_float(mb[ws * 6 + 3]);
        cz = __uint_as_float(mb[ws * 6 + 4]);
        far = (int)wi;   // global index for center_idx bookkeeping
    }
}

// -------------------- kNN: 4 centers/CTA, recompute-d2 --------------------
#define KNN_C 4
__global__ void __launch_bounds__(256) knn_kernel() {
    __shared__ int hist[KNN_C * 2048];
    __shared__ int scansm[256];
    __shared__ int selbin[KNN_C], lessc[KNN_C], candc[KNN_C];

    const int bid = blockIdx.x;
    const int gid0 = bid * KNN_C;
    const int b = gid0 >> 9;
    const int tid = threadIdx.x;

    float cx[KNN_C], cy[KNN_C], cz[KNN_C], cc2[KNN_C];
#pragma unroll
    for (int c = 0; c < KNN_C; c++) {
        cx[c] = g_centers[(gid0 + c) * 3 + 0];
        cy[c] = g_centers[(gid0 + c) * 3 + 1];
        cz[c] = g_centers[(gid0 + c) * 3 + 2];
        cc2[c] = __fmaf_rn(cx[c], cx[c], __fmaf_rn(cy[c], cy[c], __fmul_rn(cz[c], cz[c])));
    }
    for (int i = tid; i < KNN_C * 2048; i += 256) hist[i] = 0;
    __syncthreads();

    for (int n = tid; n < N_; n += 256) {
        float4 q = g_xyz[b * N_ + n];
#pragma unroll
        for (int c = 0; c < KNN_C; c++) {
            float d2 = dist2c(cx[c], cy[c], cz[c], cc2[c], q);
            atomicAdd(&hist[c * 2048 + (okey(d2) >> 21)], 1);
        }
    }
    __syncthreads();

    for (int c = 0; c < KNN_C; c++) {
        int* hc = hist + c * 2048;
        int s = 0;
#pragma unroll
        for (int t = 0; t < 8; ++t) s += hc[tid * 8 + t];
        scansm[tid] = s;
        __syncthreads();
        for (int off = 1; off < 256; off <<= 1) {
            int v = (tid >= off) ? scansm[tid - off] : 0;
            __syncthreads();
            scansm[tid] += v;
            __syncthreads();
        }
        int excl = scansm[tid] - s;
        if (excl < K_ && excl + s >= K_) {
            int cum = excl;
#pragma unroll
            for (int t = 0; t < 8; ++t) {
                int cc = hc[tid * 8 + t];
                if (cum + cc >= K_) { selbin[c] = tid * 8 + t; break; }
                cum += cc;
            }
        }
        __syncthreads();
    }
    if (tid < KNN_C) { lessc[tid] = 0; candc[tid] = 0; }
    __syncthreads();

    for (int n = tid; n < N_; n += 256) {
        float4 q = g_xyz[b * N_ + n];
#pragma unroll
        for (int c = 0; c < KNN_C; c++) {
            float d2 = dist2c(cx[c], cy[c], cz[c], cc2[c], q);
            unsigned u = okey(d2);
            int bin = (int)(u >> 21);
            if (bin < selbin[c]) {
                int p = atomicAdd(&lessc[c], 1);
                g_gidx[(size_t)(gid0 + c) * K_ + p] = n;
            } else if (bin == selbin[c]) {
                int e = atomicAdd(&candc[c], 1);
                if (e < 1024) {
                    hist[c * 2048 + e] = n;
                    hist[c * 2048 + 1024 + e] = (int)u;
                }
            }
        }
    }
    __syncthreads();

    for (int c = 0; c < KNN_C; c++) {
        int less = lessc[c];
        int cnt = candc[c];
        int need = K_ - less;
        int* gout = g_gidx + (size_t)(gid0 + c) * K_;
        if (cnt <= 1024) {
            int* cl = hist + c * 2048;
            for (int i = tid; i < cnt; i += 256) {
                int ni = cl[i];
                unsigned ui = (unsigned)cl[1024 + i];
                int rnk = 0;
                for (int j = 0; j < cnt; ++j) {
                    unsigned uj = (unsigned)cl[1024 + j];
                    int nj = cl[j];
                    rnk += (uj < ui || (uj == ui && nj < ni)) ? 1 : 0;
                }
                if (rnk < need) gout[less + rnk] = ni;
            }
        } else if (tid == 0) {
            int cc = 0;
            for (int n = 0; n < N_ && cc < need; ++n) {
                float4 q = g_xyz[b * N_ + n];
                float d2 = dist2c(cx[c], cy[c], cz[c], cc2[c], q);
                if ((int)(okey(d2) >> 21) == selbin[c]) { gout[less + cc] = n; ++cc; }
            }
        }
    }
}

// -------------------- mma.sync tf32 encoder (R8 version) --------------------
template<int KT, int NPH, int NPT, int SIN, int SOUT>
__device__ __forceinline__ void mma_layer_bn(
    const uint32_t* __restrict__ As, uint32_t* __restrict__ Ds,
    const uint32_t* __restrict__ wf, int p0,
    const float* __restrict__ ps, const float* __restrict__ po,
    int warp, int lane)
{
    float acc[2 * NPH][4];
#pragma unroll
    for (int t = 0; t < 2 * NPH; t++)
#pragma unroll
        for (int q = 0; q < 4; q++) acc[t][q] = 0.0f;
    const int g = lane >> 2, tig = lane & 3;
    const int row = warp * 16 + g;
#pragma unroll 2
    for (int kt = 0; kt < KT; kt++) {
        const uint32_t* ap = As + row * SIN + kt * 8 + tig;
        uint32_t a0 = ap[0], a2 = ap[4];
        uint32_t a1 = ap[8 * SIN], a3 = ap[8 * SIN + 4];
        const uint4* wp = (const uint4*)wf + ((size_t)(kt * NPT + p0)) * 32 + lane;
#pragma unroll
        for (int pp = 0; pp < NPH; pp++) {
            uint4 W = __ldg(wp + pp * 32);
            mma_tf32(acc[2 * pp],     a0, a1, a2, a3, W.x, W.y);
            mma_tf32(acc[2 * pp + 1], a0, a1, a2, a3, W.z, W.w);
        }
    }
#pragma unroll
    for (int t = 0; t < 2 * NPH; t++) {
        int j0 = (p0 * 2 + t) * 8 + 2 * tig;
        float s0 = __ldg(ps + j0), s1 = __ldg(ps + j0 + 1);
        float q0 = __ldg(po + j0), q1 = __ldg(po + j0 + 1);
        uint32_t* d0 = Ds + row * SOUT + j0;
        uint32_t* d1 = Ds + (row + 8) * SOUT + j0;
        d0[0] = f2tf32(fmaxf(fmaf(acc[t][0], s0, q0), 0.0f));
        d0[1] = f2tf32(fmaxf(fmaf(acc[t][1], s1, q1), 0.0f));
        d1[0] = f2tf32(fmaxf(fmaf(acc[t][2], s0, q0), 0.0f));
        d1[1] = f2tf32(fmaxf(fmaf(acc[t][3], s1, q1), 0.0f));
    }
}

template<int KT, int NPH, int NPT, int SIN>
__device__ __forceinline__ void mma_layer_max(
    const uint32_t* __restrict__ As, const uint32_t* __restrict__ wf, int p0,
    float* __restrict__ maxw, int warp, int lane)
{
    float acc[2 * NPH][4];
#pragma unroll
    for (int t = 0; t < 2 * NPH; t++)
#pragma unroll
        for (int q = 0; q < 4; q++) acc[t][q] = 0.0f;
    const int g = lane >> 2, tig = lane & 3;
    const int row = warp * 16 + g;
#pragma unroll 2
    for (int kt = 0; kt < KT; kt++) {
        const uint32_t* ap = As + row * SIN + kt * 8 + tig;
        uint32_t a0 = ap[0], a2 = ap[4];
        uint32_t a1 = ap[8 * SIN], a3 = ap[8 * SIN + 4];
        const uint4* wp = (const uint4*)wf + ((size_t)(kt * NPT + p0)) * 32 + lane;
#pragma unroll
        for (int pp = 0; pp < NPH; pp++) {
            uint4 W = __ldg(wp + pp * 32);
            mma_tf32(acc[2 * pp],     a0, a1, a2, a3, W.x, W.y);
            mma_tf32(acc[2 * pp + 1], a0, a1, a2, a3, W.z, W.w);
        }
    }
#pragma unroll
    for (int t = 0; t < 2 * NPH; t++) {
        int j0 = (p0 * 2 + t) * 8 + 2 * tig;
        float m0 = fmaxf(acc[t][0], acc[t][2]);
        float m1 = fmaxf(acc[t][1], acc[t][3]);
#pragma unroll
        for (int o = 4; o < 32; o <<= 1) {
            m0 = fmaxf(m0, __shfl_xor_sync(0xffffffffu, m0, o));
            m1 = fmaxf(m1, __shfl_xor_sync(0xffffffffu, m1, o));
        }
        if (g == 0) {
            maxw[warp * 392 + j0] = m0;
            maxw[warp * 392 + j0 + 1] = m1;
        }
    }
}

__global__ void __launch_bounds__(128, 2) encoder_kernel(
    const float* __restrict__ pts, const float* __restrict__ b4,
    float* __restrict__ tokens)
{
    extern __shared__ uint32_t esm[];
    uint32_t* X = esm;
    uint32_t* Y = esm + 16640;
    float* maxw = (float*)Y;

    const int tid = threadIdx.x;
    const int warp = tid >> 5, lane = tid & 31;

    if (tid < 64) {
        int gid2 = blockIdx.x * 2 + (tid >> 5);
        int b = gid2 >> 9;
        int n = g_gidx[(size_t)gid2 * K_ + (tid & 31)];
        const float* p = pts + (size_t)(b * N_ + n) * C_;
        float cx = g_centers[gid2 * 3 + 0];
        float cy = g_centers[gid2 * 3 + 1];
        float cz = g_centers[gid2 * 3 + 2];
        float x = p[0], y = p[1], z = p[2];
        uint32_t* r = Y + tid * 36;
        r[0] = f2tf32(x - cx); r[1] = f2tf32(y - cy); r[2] = f2tf32(z - cz);
        r[3] = f2tf32(x); r[4] = f2tf32(y); r[5] = f2tf32(z);
        r[6] = f2tf32(p[3]); r[7] = f2tf32(p[4]); r[8] = f2tf32(p[5]);
#pragma unroll
        for (int c = 9; c < 16; c++) r[c] = 0u;
    }
    __syncthreads();

    mma_layer_bn<2, 4, 4, 36, 68>(Y, X, g_wf1, 0, g_ps, g_po, warp, lane);
    __syncwarp();
    mma_layer_bn<8, 8, 8, 68, 132>(X, Y, g_wf2, 0, g_ps + 64, g_po + 64, warp, lane);
    __syncwarp();
    mma_layer_bn<16, 8, 16, 132, 260>(Y, X, g_wf3, 0, g_ps + 192, g_po + 192, warp, lane);
    mma_layer_bn<16, 8, 16, 132, 260>(Y, X, g_wf3, 8, g_ps + 192, g_po + 192, warp, lane);
    __syncwarp();
    __syncthreads();
    mma_layer_max<32, 12, 24, 260>(X, g_wf4, 0,  maxw, warp, lane);
    mma_layer_max<32, 12, 24, 260>(X, g_wf4, 12, maxw, warp, lane);
    __syncthreads();

    for (int i = tid; i < 768; i += 128) {
        int g = i / 384, col = i - g * 384;
        float mx = fmaxf(maxw[(2 * g) * 392 + col], maxw[(2 * g + 1) * 392 + col]);
        tokens[(size_t)(blockIdx.x * 2 + g) * 384 + col] = mx + __ldg(b4 + col);
    }
}

// -------------------- positional MLP: 8 centers/CTA --------------------
__global__ void __launch_bounds__(384) pos_kernel(
    const float* __restrict__ pw1, const float* __restrict__ pb1,
    const float* __restrict__ pw2, const float* __restrict__ pb2,
    float* __restrict__ tokens)
{
    __shared__ float h[8 * 128];
    const int gid0 = blockIdx.x * 8;
    const int tid = threadIdx.x;

    for (int idx = tid; idx < 8 * 128; idx += 384) {
        int c = idx >> 7, col = idx & 127;
        float cx = g_centers[(gid0 + c) * 3 + 0];
        float cy = g_centers[(gid0 + c) * 3 + 1];
        float cz = g_centers[(gid0 + c) * 3 + 2];
        float t = cx * __ldg(pw1 + col) + cy * __ldg(pw1 + 128 + col)
                + cz * __ldg(pw1 + 256 + col) + __ldg(pb1 + col);
        h[idx] = 0.5f * t * (1.0f + erff(t * 0.70710678118654752f));
    }
    __syncthreads();

    const int col = tid;
    float acc[8];
    float bj = __ldg(pb2 + col);
#pragma unroll
    for (int c = 0; c < 8; c++) acc[c] = bj;
#pragma unroll 2
    for (int k = 0; k < 128; ++k) {
        float w = __ldg(pw2 + (size_t)k * 384 + col);
#pragma unroll
        for (int c = 0; c < 8; c++)
            acc[c] = fmaf(h[c * 128 + k], w, acc[c]);
    }
#pragma unroll
    for (int c = 0; c < 8; c++)
        tokens[(size_t)(gid0 + c) * 384 + col] += acc[c];
}

// -------------------- launch --------------------
extern "C" void kernel_launch(void* const* d_in, const int* in_sizes, int n_in,
                              void* d_out, int out_size)
{
    const float* pts = (const float*)d_in[0];
    const float* w1 = (const float*)d_in[1],  *b1 = (const float*)d_in[2];
    const float* g1 = (const float*)d_in[3],  *be1 = (const float*)d_in[4];
    const float* m1 = (const float*)d_in[5],  *v1 = (const float*)d_in[6];
    const float* w2 = (const float*)d_in[7],  *b2 = (const float*)d_in[8];
    const float* g2 = (const float*)d_in[9],  *be2 = (const float*)d_in[10];
    const float* m2 = (const float*)d_in[11], *v2 = (const float*)d_in[12];
    const float* w3 = (const float*)d_in[13], *b3 = (const float*)d_in[14];
    const float* g3 = (const float*)d_in[15], *be3 = (const float*)d_in[16];
    const float* m3 = (const float*)d_in[17], *v3 = (const float*)d_in[18];
    const float* w4 = (const float*)d_in[19], *b4 = (const float*)d_in[20];
    const float* pw1 = (const float*)d_in[21], *pb1 = (const float*)d_in[22];
    const float* pw2 = (const float*)d_in[23], *pb2 = (const float*)d_in[24];

    float* out = (float*)d_out;
    float* tokens = out;
    float* centers_out =
        (out_size >= B_ * M_ * 384 + B_ * M_ * 3) ? (out + (size_t)B_ * M_ * 384)
                                                  : nullptr;

    const int FPS_SMEM = (16448 + 48) * 4;    // 65,984 B
    const int ENC_SMEM = (16640 + 8448) * 4;  // 100,352 B

    cudaFuncSetAttribute(fps_kernel, cudaFuncAttributeMaxDynamicSharedMemorySize, FPS_SMEM);
    cudaFuncSetAttribute(encoder_kernel, cudaFuncAttributeMaxDynamicSharedMemorySize, ENC_SMEM);

    const int TOT = T1 + T2 + T3 + T4;
    prep_frag_all<<<(TOT + 255) / 256, 256>>>(w1, w2, w3, w4);
    prep_p_all<<<2, 256>>>(b1, g1, be1, m1, v1, b2, g2, be2, m2, v2, b3, g3, be3, m3, v3);
    pack_kernel<<<(B_ * N_ + 255) / 256, 256>>>(pts);
    fps_kernel<<<B_ * 4, 1024, FPS_SMEM>>>(centers_out);
    knn_kernel<<<B_ * M_ / KNN_C, 256>>>();
    encoder_kernel<<<B_ * M_ / 2, 128, ENC_SMEM>>>(pts, b4, tokens);
    pos_kernel<<<B_ * M_ / 8, 384>>>(pw1, pb1, pw2, pb2, tokens);
}

// round 14
// speedup vs baseline: 1.3636x; 1.0114x over previous
#include <cuda_runtime.h>
#include <math.h>
#include <stdint.h>

#define B_ 8
#define N_ 16384
#define M_ 512
#define K_ 32
#define C_ 6
#define FPS_P 4096      // points per FPS CTA (4-CTA cluster)

// -------------------- scratch --------------------
__device__ int    g_center_idx[B_ * M_];
__device__ float  g_centers[B_ * M_ * 3];
__device__ int    g_gidx[B_ * M_ * K_];
__device__ float4 g_xyz[B_ * N_];
__device__ __align__(16) uint32_t g_wf1[2 * 4 * 128];
__device__ __align__(16) uint32_t g_wf2[8 * 8 * 128];
__device__ __align__(16) uint32_t g_wf3[16 * 16 * 128];
__device__ __align__(16) uint32_t g_wf4[32 * 24 * 128];
__device__ float g_ps[448], g_po[448];

// -------------------- helpers --------------------
__device__ __forceinline__ unsigned okey(float f) {
    unsigned u = __float_as_uint(f);
    unsigned mask = (u & 0x80000000u) ? 0xFFFFFFFFu : 0x80000000u;
    return u ^ mask;
}
__device__ __forceinline__ uint32_t f2tf32(float x) {
    uint32_t r;
    asm("cvt.rna.tf32.f32 %0, %1;" : "=r"(r) : "f"(x));
    return r;
}
__device__ __forceinline__ void mma_tf32(float* c, uint32_t a0, uint32_t a1,
                                         uint32_t a2, uint32_t a3,
                                         uint32_t b0, uint32_t b1) {
    asm volatile(
        "mma.sync.aligned.m16n8k8.row.col.f32.tf32.tf32.f32 "
        "{%0,%1,%2,%3}, {%4,%5,%6,%7}, {%8,%9}, {%0,%1,%2,%3};"
        : "+f"(c[0]), "+f"(c[1]), "+f"(c[2]), "+f"(c[3])
        : "r"(a0), "r"(a1), "r"(a2), "r"(a3), "r"(b0), "r"(b1));
}
__device__ __forceinline__ uint32_t smem_u32(const void* p) {
    uint32_t a;
    asm("{ .reg .u64 t; cvta.to.shared.u64 t, %1; cvt.u32.u64 %0, t; }" : "=r"(a) : "l"(p));
    return a;
}
__device__ __forceinline__ uint32_t mapa_sh(uint32_t addr, uint32_t rank) {
    uint32_t r;
    asm("mapa.shared::cluster.u32 %0, %1, %2;" : "=r"(r) : "r"(addr), "r"(rank));
    return r;
}
__device__ __forceinline__ void stsc_u64(uint32_t a, unsigned long long v) {
    asm volatile("st.shared::cluster.b64 [%0], %1;" :: "r"(a), "l"(v) : "memory");
}
__device__ __forceinline__ void stsc_u32(uint32_t a, unsigned v) {
    asm volatile("st.shared::cluster.b32 [%0], %1;" :: "r"(a), "r"(v) : "memory");
}
__device__ __forceinline__ void cluster_sync_() {
    asm volatile("barrier.cluster.arrive.aligned;" ::: "memory");
    asm volatile("barrier.cluster.wait.aligned;" ::: "memory");
}
__device__ __forceinline__ unsigned long long packu64(unsigned lo, unsigned hi) {
    unsigned long long d;
    asm("mov.b64 %0, {%1, %2};" : "=l"(d) : "r"(lo), "r"(hi));
    return d;
}
__device__ __forceinline__ float dist2c(float cx, float cy, float cz, float cc2,
                                        float4 q) {
    float dot = __fmaf_rn(cx, q.x, __fmaf_rn(cy, q.y, __fmul_rn(cz, q.z)));
    return __fadd_rn(__fmaf_rn(-2.0f, dot, cc2), q.w);
}

// -------------------- merged weight-fragment prep --------------------
__device__ __forceinline__ void frag_one(const float* w, uint32_t* dst,
                                         int CIN, int DOUT, int idx) {
    int r = idx & 1, o = (idx >> 1) & 1, lane = (idx >> 2) & 31;
    int rest = idx >> 7;
    int np = DOUT / 16;
    int p = rest % np, kt = rest / np;
    int nt = 2 * p + o;
    int n = nt * 8 + (lane >> 2);
    int k = kt * 8 + (lane & 3) + 4 * r;
    float v = (k < CIN) ? w[(size_t)k * DOUT + n] : 0.0f;
    dst[idx] = f2tf32(v);
}
#define T1 (2 * 4 * 128)
#define T2 (8 * 8 * 128)
#define T3 (16 * 16 * 128)
#define T4 (32 * 24 * 128)
__global__ void prep_frag_all(const float* __restrict__ w1, const float* __restrict__ w2,
                              const float* __restrict__ w3, const float* __restrict__ w4) {
    int idx = blockIdx.x * blockDim.x + threadIdx.x;
    if (idx < T1) { frag_one(w1, g_wf1, 9, 64, idx); return; }
    idx -= T1;
    if (idx < T2) { frag_one(w2, g_wf2, 64, 128, idx); return; }
    idx -= T2;
    if (idx < T3) { frag_one(w3, g_wf3, 128, 256, idx); return; }
    idx -= T3;
    if (idx < T4) { frag_one(w4, g_wf4, 256, 384, idx); }
}

__global__ void prep_p_all(
    const float* __restrict__ b1, const float* __restrict__ g1,
    const float* __restrict__ be1, const float* __restrict__ m1, const float* __restrict__ v1,
    const float* __restrict__ b2, const float* __restrict__ g2,
    const float* __restrict__ be2, const float* __restrict__ m2, const float* __restrict__ v2,
    const float* __restrict__ b3, const float* __restrict__ g3,
    const float* __restrict__ be3, const float* __restrict__ m3, const float* __restrict__ v3)
{
    int i = blockIdx.x * blockDim.x + threadIdx.x;
    if (i >= 448) return;
    const float *b, *g, *be, *m, *v;
    int off;
    if (i < 64)       { b = b1; g = g1; be = be1; m = m1; v = v1; off = i; }
    else if (i < 192) { b = b2; g = g2; be = be2; m = m2; v = v2; off = i - 64; }
    else              { b = b3; g = g3; be = be3; m = m3; v = v3; off = i - 192; }
    float sc = g[off] * rsqrtf(v[off] + 1e-5f);
    g_ps[i] = sc;
    g_po[i] = (b[off] - m[off]) * sc + be[off];
}

// -------------------- pack xyz --------------------
__global__ void pack_kernel(const float* __restrict__ pts) {
    int i = blockIdx.x * blockDim.x + threadIdx.x;
    if (i < B_ * N_) {
        const float* p = pts + (size_t)i * C_;
        float x = p[0], y = p[1], z = p[2];
        g_xyz[i] = make_float4(x, y, z, x * x + y * y + z * z);
    }
}

// -------------------- FPS: 4-CTA cluster, register-resident scan ----------------
// smem: sq float4[4096] | rk[32] ri[32] @16384 floats | mail u32[2][4][6] @16448
__global__ void __launch_bounds__(1024, 1) __cluster_dims__(4, 1, 1)
fps_kernel(float* centers_out) {
    extern __shared__ float fsm[];
    float4*   sq = (float4*)fsm;
    unsigned* rk = (unsigned*)(fsm + 16384);
    unsigned* ri = rk + 32;
    unsigned* mail = (unsigned*)(fsm + 16448);   // 2 buffers x 4 records x 6 u32
    const float* mailf = (const float*)mail;

    const int b = blockIdx.x >> 2;
    const uint32_t rank = blockIdx.x & 3;
    const int tid = threadIdx.x;
    const int lane = tid & 31, wid = tid >> 5;
    const uint32_t mail_b = smem_u32(mail);

    // stage points to SMEM (for winner lookup) and registers (for the scan)
    float px[4], py[4], pz[4];
#pragma unroll
    for (int j = 0; j < 4; j++) {
        int n = j * 1024 + tid;
        float4 q = g_xyz[b * N_ + rank * FPS_P + n];
        sq[n] = q;
        px[j] = q.x; py[j] = q.y; pz[j] = q.z;
    }
    float dist[4];
#pragma unroll
    for (int j = 0; j < 4; j++) dist[j] = 1e10f;
    __syncthreads();

    if (rank == 0 && tid == 0) {
        float4 q = sq[0];
        for (uint32_t r = 0; r < 4; r++) {
            uint32_t a = mapa_sh(mail_b + 96, r);   // buffer 1, record 0
            stsc_u64(a + 8, packu64(__float_as_uint(q.x), __float_as_uint(q.y)));
            stsc_u32(a + 16, __float_as_uint(q.z));
        }
    }
    cluster_sync_();
    int far = 0;
    float cx = mailf[24 + 2], cy = mailf[24 + 3], cz = mailf[24 + 4];

    for (int it = 0; it < M_; ++it) {
        if (rank == 0 && tid == 0) {
            g_center_idx[b * M_ + it] = far;
            float* gc = g_centers + (size_t)(b * M_ + it) * 3;
            gc[0] = cx; gc[1] = cy; gc[2] = cz;
            if (centers_out) {
                float* oc = centers_out + (size_t)(b * M_ + it) * 3;
                oc[0] = cx; oc[1] = cy; oc[2] = cz;
            }
        }
        float bd = -1.0f; int bi = 0x7fffffff;
#pragma unroll
        for (int j = 0; j < 4; j++) {
            float dx = px[j] - cx, dy = py[j] - cy, dz = pz[j] - cz;
            float d = dx * dx + dy * dy + dz * dz;
            float nd = fminf(dist[j], d);
            dist[j] = nd;
            if (nd > bd) { bd = nd; bi = j * 1024 + tid; }
        }
        unsigned key = okey(bd);
        unsigned kmax = __reduce_max_sync(0xffffffffu, key);
        unsigned cnd = (key == kmax) ? (unsigned)bi : 0xffffffffu;
        unsigned imin = __reduce_min_sync(0xffffffffu, cnd);
        if (lane == 0) { rk[wid] = kmax; ri[wid] = imin; }
        __syncthreads();
        const int p = it & 1;
        if (wid == 0) {
            unsigned k2 = rk[lane], i2 = ri[lane];
            unsigned kmax2 = __reduce_max_sync(0xffffffffu, k2);
            unsigned cnd2 = (k2 == kmax2) ? i2 : 0xffffffffu;
            unsigned imin2 = __reduce_min_sync(0xffffffffu, cnd2);
            if (lane < 4) {   // redux broadcasts: lanes 0..3 ship record to rank=lane
                int li = (int)imin2;
                unsigned gi = rank * FPS_P + (unsigned)li;
                float4 q = sq[li];
                uint32_t a = mapa_sh(mail_b + p * 96 + rank * 24, (uint32_t)lane);
                stsc_u64(a, packu64(kmax2, gi));
                stsc_u64(a + 8, packu64(__float_as_uint(q.x), __float_as_uint(q.y)));
                stsc_u32(a + 16, __float_as_uint(q.z));
            }
        }
        cluster_sync_();
        const unsigned* mb = mail + p * 24;
        unsigned wkey = mb[0]; unsigned wi = mb[1]; int ws = 0;
#pragma unroll
        for (int s = 1; s < 4; s++) {
            unsigned k = mb[s * 6]; unsigned i = mb[s * 6 + 1];
            if (k > wkey || (k == wkey && i < wi)) { wkey = k; wi = i; ws = s; }
        }
        cx = __uint_as_float(mb[ws * 6 + 2]);
        cy = __uint_as_float(mb[ws * 6 + 3]);
        cz = __uint_as_float(mb[ws * 6 + 4]);
        far = (int)wi;
    }
}

// -------------------- kNN: 4 centers/CTA, recompute-d2 --------------------
#define KNN_C 4
__global__ void __launch_bounds__(256) knn_kernel() {
    __shared__ int hist[KNN_C * 2048];
    __shared__ int scansm[256];
    __shared__ int selbin[KNN_C], lessc[KNN_C], candc[KNN_C];

    const int bid = blockIdx.x;
    const int gid0 = bid * KNN_C;
    const int b = gid0 >> 9;
    const int tid = threadIdx.x;

    float cx[KNN_C], cy[KNN_C], cz[KNN_C], cc2[KNN_C];
#pragma unroll
    for (int c = 0; c < KNN_C; c++) {
        cx[c] = g_centers[(gid0 + c) * 3 + 0];
        cy[c] = g_centers[(gid0 + c) * 3 + 1];
        cz[c] = g_centers[(gid0 + c) * 3 + 2];
        cc2[c] = __fmaf_rn(cx[c], cx[c], __fmaf_rn(cy[c], cy[c], __fmul_rn(cz[c], cz[c])));
    }
    for (int i = tid; i < KNN_C * 2048; i += 256) hist[i] = 0;
    __syncthreads();

    for (int n = tid; n < N_; n += 256) {
        float4 q = g_xyz[b * N_ + n];
#pragma unroll
        for (int c = 0; c < KNN_C; c++) {
            float d2 = dist2c(cx[c], cy[c], cz[c], cc2[c], q);
            atomicAdd(&hist[c * 2048 + (okey(d2) >> 21)], 1);
        }
    }
    __syncthreads();

    for (int c = 0; c < KNN_C; c++) {
        int* hc = hist + c * 2048;
        int s = 0;
#pragma unroll
        for (int t = 0; t < 8; ++t) s += hc[tid * 8 + t];
        scansm[tid] = s;
        __syncthreads();
        for (int off = 1; off < 256; off <<= 1) {
            int v = (tid >= off) ? scansm[tid - off] : 0;
            __syncthreads();
            scansm[tid] += v;
            __syncthreads();
        }
        int excl = scansm[tid] - s;
        if (excl < K_ && excl + s >= K_) {
            int cum = excl;
#pragma unroll
            for (int t = 0; t < 8; ++t) {
                int cc = hc[tid * 8 + t];
                if (cum + cc >= K_) { selbin[c] = tid * 8 + t; break; }
                cum += cc;
            }
        }
        __syncthreads();
    }
    if (tid < KNN_C) { lessc[tid] = 0; candc[tid] = 0; }
    __syncthreads();

    for (int n = tid; n < N_; n += 256) {
        float4 q = g_xyz[b * N_ + n];
#pragma unroll
        for (int c = 0; c < KNN_C; c++) {
            float d2 = dist2c(cx[c], cy[c], cz[c], cc2[c], q);
            unsigned u = okey(d2);
            int bin = (int)(u >> 21);
            if (bin < selbin[c]) {
                int p = atomicAdd(&lessc[c], 1);
                g_gidx[(size_t)(gid0 + c) * K_ + p] = n;
            } else if (bin == selbin[c]) {
                int e = atomicAdd(&candc[c], 1);
                if (e < 1024) {
                    hist[c * 2048 + e] = n;
                    hist[c * 2048 + 1024 + e] = (int)u;
                }
            }
        }
    }
    __syncthreads();

    for (int c = 0; c < KNN_C; c++) {
        int less = lessc[c];
        int cnt = candc[c];
        int need = K_ - less;
        int* gout = g_gidx + (size_t)(gid0 + c) * K_;
        if (cnt <= 1024) {
            int* cl = hist + c * 2048;
            for (int i = tid; i < cnt; i += 256) {
                int ni = cl[i];
                unsigned ui = (unsigned)cl[1024 + i];
                int rnk = 0;
                for (int j = 0; j < cnt; ++j) {
                    unsigned uj = (unsigned)cl[1024 + j];
                    int nj = cl[j];
                    rnk += (uj < ui || (uj == ui && nj < ni)) ? 1 : 0;
                }
                if (rnk < need) gout[less + rnk] = ni;
            }
        } else if (tid == 0) {
            int cc = 0;
            for (int n = 0; n < N_ && cc < need; ++n) {
                float4 q = g_xyz[b * N_ + n];
                float d2 = dist2c(cx[c], cy[c], cz[c], cc2[c], q);
                if ((int)(okey(d2) >> 21) == selbin[c]) { gout[less + cc] = n; ++cc; }
            }
        }
    }
}

// -------------------- mma.sync tf32 encoder: 4 groups/CTA (M=128) --------------
template<int KT, int NPH, int NPT, int SIN, int SOUT>
__device__ __forceinline__ void mma_layer_bn(
    const uint32_t* __restrict__ As, uint32_t* __restrict__ Ds,
    const uint32_t* __restrict__ wf, int p0,
    const float* __restrict__ ps, const float* __restrict__ po,
    int warp, int lane)
{
    float acc[2 * NPH][4];
#pragma unroll
    for (int t = 0; t < 2 * NPH; t++)
#pragma unroll
        for (int q = 0; q < 4; q++) acc[t][q] = 0.0f;
    const int g = lane >> 2, tig = lane & 3;
    const int row = warp * 16 + g;
#pragma unroll 2
    for (int kt = 0; kt < KT; kt++) {
        const uint32_t* ap = As + row * SIN + kt * 8 + tig;
        uint32_t a0 = ap[0], a2 = ap[4];
        uint32_t a1 = ap[8 * SIN], a3 = ap[8 * SIN + 4];
        const uint4* wp = (const uint4*)wf + ((size_t)(kt * NPT + p0)) * 32 + lane;
#pragma unroll
        for (int pp = 0; pp < NPH; pp++) {
            uint4 W = __ldg(wp + pp * 32);
            mma_tf32(acc[2 * pp],     a0, a1, a2, a3, W.x, W.y);
            mma_tf32(acc[2 * pp + 1], a0, a1, a2, a3, W.z, W.w);
        }
    }
#pragma unroll
    for (int t = 0; t < 2 * NPH; t++) {
        int j0 = (p0 * 2 + t) * 8 + 2 * tig;
        float s0 = __ldg(ps + j0), s1 = __ldg(ps + j0 + 1);
        float q0 = __ldg(po + j0), q1 = __ldg(po + j0 + 1);
        uint32_t* d0 = Ds + row * SOUT + j0;
        uint32_t* d1 = Ds + (row + 8) * SOUT + j0;
        d0[0] = f2tf32(fmaxf(fmaf(acc[t][0], s0, q0), 0.0f));
        d0[1] = f2tf32(fmaxf(fmaf(acc[t][1], s1, q1), 0.0f));
        d1[0] = f2tf32(fmaxf(fmaf(acc[t][2], s0, q0), 0.0f));
        d1[1] = f2tf32(fmaxf(fmaf(acc[t][3], s1, q1), 0.0f));
    }
}

template<int KT, int NPH, int NPT, int SIN>
__device__ __forceinline__ void mma_layer_max(
    const uint32_t* __restrict__ As, const uint32_t* __restrict__ wf, int p0,
    float* __restrict__ maxw, int warp, int lane)
{
    float acc[2 * NPH][4];
#pragma unroll
    for (int t = 0; t < 2 * NPH; t++)
#pragma unroll
        for (int q = 0; q < 4; q++) acc[t][q] = 0.0f;
    const int g = lane >> 2, tig = lane & 3;
    const int row = warp * 16 + g;
#pragma unroll 2
    for (int kt = 0; kt < KT; kt++) {
        const uint32_t* ap = As + row * SIN + kt * 8 + tig;
        uint32_t a0 = ap[0], a2 = ap[4];
        uint32_t a1 = ap[8 * SIN], a3 = ap[8 * SIN + 4];
        const uint4* wp = (const uint4*)wf + ((size_t)(kt * NPT + p0)) * 32 + lane;
#pragma unroll
        for (int pp = 0; pp < NPH; pp++) {
            uint4 W = __ldg(wp + pp * 32);
            mma_tf32(acc[2 * pp],     a0, a1, a2, a3, W.x, W.y);
            mma_tf32(acc[2 * pp + 1], a0, a1, a2, a3, W.z, W.w);
        }
    }
#pragma unroll
    for (int t = 0; t < 2 * NPH; t++) {
        int j0 = (p0 * 2 + t) * 8 + 2 * tig;
        float m0 = fmaxf(acc[t][0], acc[t][2]);
        float m1 = fmaxf(acc[t][1], acc[t][3]);
#pragma unroll
        for (int o = 4; o < 32; o <<= 1) {
            m0 = fmaxf(m0, __shfl_xor_sync(0xffffffffu, m0, o));
            m1 = fmaxf(m1, __shfl_xor_sync(0xffffffffu, m1, o));
        }
        if (g == 0) {
            maxw[warp * 392 + j0] = m0;
            maxw[warp * 392 + j0 + 1] = m1;
        }
    }
}

// SMEM u32: X[33280] @0 (128 rows x 260), Y @33280 (128 rows x 132 = 16896)
__global__ void __launch_bounds__(256, 1) encoder_kernel(
    const float* __restrict__ pts, const float* __restrict__ b4,
    float* __restrict__ tokens)
{
    extern __shared__ uint32_t esm[];
    uint32_t* X = esm;
    uint32_t* Y = esm + 33280;
    float* maxw = (float*)Y;    // aliases Y during L4 (needs 8*392*4 B)

    const int tid = threadIdx.x;
    const int warp = tid >> 5, lane = tid & 31;

    if (tid < 128) {
        int gid4 = blockIdx.x * 4 + (tid >> 5);
        int b = gid4 >> 9;
        int n = g_gidx[(size_t)gid4 * K_ + (tid & 31)];
        const float* p = pts + (size_t)(b * N_ + n) * C_;
        float cx = g_centers[gid4 * 3 + 0];
        float cy = g_centers[gid4 * 3 + 1];
        float cz = g_centers[gid4 * 3 + 2];
        float x = p[0], y = p[1], z = p[2];
        uint32_t* r = Y + tid * 36;
        r[0] = f2tf32(x - cx); r[1] = f2tf32(y - cy); r[2] = f2tf32(z - cz);
        r[3] = f2tf32(x); r[4] = f2tf32(y); r[5] = f2tf32(z);
        r[6] = f2tf32(p[3]); r[7] = f2tf32(p[4]); r[8] = f2tf32(p[5]);
#pragma unroll
        for (int c = 9; c < 16; c++) r[c] = 0u;
    }
    __syncthreads();

    mma_layer_bn<2, 4, 4, 36, 68>(Y, X, g_wf1, 0, g_ps, g_po, warp, lane);
    __syncwarp();
    mma_layer_bn<8, 8, 8, 68, 132>(X, Y, g_wf2, 0, g_ps + 64, g_po + 64, warp, lane);
    __syncwarp();
    mma_layer_bn<16, 8, 16, 132, 260>(Y, X, g_wf3, 0, g_ps + 192, g_po + 192, warp, lane);
    mma_layer_bn<16, 8, 16, 132, 260>(Y, X, g_wf3, 8, g_ps + 192, g_po + 192, warp, lane);
    __syncwarp();
    __syncthreads();   // Y reused as maxw
    mma_layer_max<32, 12, 24, 260>(X, g_wf4, 0,  maxw, warp, lane);
    mma_layer_max<32, 12, 24, 260>(X, g_wf4, 12, maxw, warp, lane);
    __syncthreads();

    for (int i = tid; i < 1536; i += 256) {
        int g = i / 384, col = i - g * 384;
        float mx = fmaxf(maxw[(2 * g) * 392 + col], maxw[(2 * g + 1) * 392 + col]);
        tokens[(size_t)(blockIdx.x * 4 + g) * 384 + col] = mx + __ldg(b4 + col);
    }
}

// -------------------- positional MLP: 8 centers/CTA --------------------
__global__ void __launch_bounds__(384) pos_kernel(
    const float* __restrict__ pw1, const float* __restrict__ pb1,
    const float* __restrict__ pw2, const float* __restrict__ pb2,
    float* __restrict__ tokens)
{
    __shared__ float h[8 * 128];
    const int gid0 = blockIdx.x * 8;
    const int tid = threadIdx.x;

    for (int idx = tid; idx < 8 * 128; idx += 384) {
        int c = idx >> 7, col = idx & 127;
        float cx = g_centers[(gid0 + c) * 3 + 0];
        float cy = g_centers[(gid0 + c) * 3 + 1];
        float cz = g_centers[(gid0 + c) * 3 + 2];
        float t = cx * __ldg(pw1 + col) + cy * __ldg(pw1 + 128 + col)
                + cz * __ldg(pw1 + 256 + col) + __ldg(pb1 + col);
        h[idx] = 0.5f * t * (1.0f + erff(t * 0.70710678118654752f));
    }
    __syncthreads();

    const int col = tid;
    float acc[8];
    float bj = __ldg(pb2 + col);
#pragma unroll
    for (int c = 0; c < 8; c++) acc[c] = bj;
#pragma unroll 2
    for (int k = 0; k < 128; ++k) {
        float w = __ldg(pw2 + (size_t)k * 384 + col);
#pragma unroll
        for (int c = 0; c < 8; c++)
            acc[c] = fmaf(h[c * 128 + k], w, acc[c]);
    }
#pragma unroll
    for (int c = 0; c < 8; c++)
        tokens[(size_t)(gid0 + c) * 384 + col] += acc[c];
}

// -------------------- launch --------------------
extern "C" void kernel_launch(void* const* d_in, const int* in_sizes, int n_in,
                              void* d_out, int out_size)
{
    const float* pts = (const float*)d_in[0];
    const float* w1 = (const float*)d_in[1],  *b1 = (const float*)d_in[2];
    const float* g1 = (const float*)d_in[3],  *be1 = (const float*)d_in[4];
    const float* m1 = (const float*)d_in[5],  *v1 = (const float*)d_in[6];
    const float* w2 = (const float*)d_in[7],  *b2 = (const float*)d_in[8];
    const float* g2 = (const float*)d_in[9],  *be2 = (const float*)d_in[10];
    const float* m2 = (const float*)d_in[11], *v2 = (const float*)d_in[12];
    const float* w3 = (const float*)d_in[13], *b3 = (const float*)d_in[14];
    const float* g3 = (const float*)d_in[15], *be3 = (const float*)d_in[16];
    const float* m3 = (const float*)d_in[17], *v3 = (const float*)d_in[18];
    const float* w4 = (const float*)d_in[19], *b4 = (const float*)d_in[20];
    const float* pw1 = (const float*)d_in[21], *pb1 = (const float*)d_in[22];
    const float* pw2 = (const float*)d_in[23], *pb2 = (const float*)d_in[24];

    float* out = (float*)d_out;
    float* tokens = out;
    float* centers_out =
        (out_size >= B_ * M_ * 384 + B_ * M_ * 3) ? (out + (size_t)B_ * M_ * 384)
                                                  : nullptr;

    const int FPS_SMEM = (16448 + 48) * 4;     // 65,984 B
    const int ENC_SMEM = (33280 + 16896) * 4;  // 200,704 B

    cudaFuncSetAttribute(fps_kernel, cudaFuncAttributeMaxDynamicSharedMemorySize, FPS_SMEM);
    cudaFuncSetAttribute(encoder_kernel, cudaFuncAttributeMaxDynamicSharedMemorySize, ENC_SMEM);

    const int TOT = T1 + T2 + T3 + T4;
    prep_frag_all<<<(TOT + 255) / 256, 256>>>(w1, w2, w3, w4);
    prep_p_all<<<2, 256>>>(b1, g1, be1, m1, v1, b2, g2, be2, m2, v2, b3, g3, be3, m3, v3);
    pack_kernel<<<(B_ * N_ + 255) / 256, 256>>>(pts);
    fps_kernel<<<B_ * 4, 1024, FPS_SMEM>>>(centers_out);
    knn_kernel<<<B_ * M_ / KNN_C, 256>>>();
    encoder_kernel<<<B_ * M_ / 4, 256, ENC_SMEM>>>(pts, b4, tokens);
    pos_kernel<<<B_ * M_ / 8, 384>>>(pw1, pb1, pw2, pb2, tokens);
}